// round 2
// baseline (speedup 1.0000x reference)
#include <cuda_runtime.h>
#include <cuda_bf16.h>
#include <cuda_fp8.h>
#include <cstdint>
#include <cstddef>

// ============================================================================
// Problem constants
// ============================================================================
#define DIM 4096
#define NELEM ((size_t)DIM * (size_t)DIM)

// GEMM tiling
#define BM 128
#define BN 128
#define BK 64                        // 64 bf16 = 128 bytes per smem row
#define NKITER (DIM / BK)            // 64
#define STAGES 3
#define TILE_BYTES (BM * BK * 2)     // 16 KB per operand tile
#define STAGE_BYTES (2 * TILE_BYTES) // 32 KB (A + B)
#define SMEM_TOTAL (STAGES * STAGE_BYTES)  // 96 KB

// ============================================================================
// Scratch (device globals — no allocations allowed)
// ============================================================================
__device__ __align__(1024) __nv_bfloat16 g_X  [NELEM];  // quantized x       [M,K] K-major
__device__ __align__(1024) __nv_bfloat16 g_W1T[NELEM];  // quantized mat1^T  [N,K] K-major
__device__ __align__(1024) __nv_bfloat16 g_W2T[NELEM];  // quantized mat2^T  [N,K] K-major
__device__ __align__(1024) float         g_H  [NELEM];  // GEMM1 output fp32 [M,N]
__device__ __align__(1024) __nv_bfloat16 g_H2 [NELEM];  // requantized H     [M,K] K-major

// ============================================================================
// Helpers
// ============================================================================
__device__ __forceinline__ uint32_t smem_u32(const void* p) {
    uint32_t a;
    asm("{ .reg .u64 t; cvta.to.shared.u64 t, %1; cvt.u32.u64 %0, t; }" : "=r"(a) : "l"(p));
    return a;
}

__device__ __forceinline__ void ldmatrix_x4(uint32_t* r, uint32_t addr) {
    asm volatile("ldmatrix.sync.aligned.m8n8.x4.shared.b16 {%0,%1,%2,%3}, [%4];"
                 : "=r"(r[0]), "=r"(r[1]), "=r"(r[2]), "=r"(r[3]) : "r"(addr));
}

__device__ __forceinline__ void mma_16816(float* c, const uint32_t* a, uint32_t b0, uint32_t b1) {
    asm volatile(
        "mma.sync.aligned.m16n8k16.row.col.f32.bf16.bf16.f32 "
        "{%0,%1,%2,%3}, {%4,%5,%6,%7}, {%8,%9}, {%0,%1,%2,%3};"
        : "+f"(c[0]), "+f"(c[1]), "+f"(c[2]), "+f"(c[3])
        : "r"(a[0]), "r"(a[1]), "r"(a[2]), "r"(a[3]), "r"(b0), "r"(b1));
}

// ============================================================================
// MX quant-dequant (exact match of the reference semantics)
// ============================================================================
__device__ __forceinline__ float mx_qd(float v, float amax) {
    if (amax == 0.0f) return 0.0f;              // all-zero block
    int e;
    frexpf(amax, &e);                           // amax = m * 2^e, m in [0.5,1)
    int se = (e - 1) - 8;                       // floor(log2(amax)) - 8 (exact)
    se = max(-127, min(127, se));
    float vs = ldexpf(v, -se);                  // v / 2^se, exact
    __nv_fp8_storage_t q = __nv_cvt_float_to_fp8(vs, __NV_SATFINITE, __NV_E4M3);
    __half_raw hr = __nv_cvt_fp8_to_halfraw(q, __NV_E4M3);
    return ldexpf(__half2float(*reinterpret_cast<__half*>(&hr)), se);
}

__device__ __forceinline__ float warp_amax(float a) {
    #pragma unroll
    for (int off = 16; off >= 1; off >>= 1)
        a = fmaxf(a, __shfl_xor_sync(0xFFFFFFFFu, a, off));
    return a;
}

// Quantize along the contiguous dim (blocks of 32), no transpose. One warp = one block.
__global__ void quant_rows_kernel(const float* __restrict__ in, __nv_bfloat16* __restrict__ out) {
    size_t idx = (size_t)blockIdx.x * blockDim.x + threadIdx.x;
    float v = in[idx];
    float amax = warp_amax(fabsf(v));
    out[idx] = __float2bfloat16(mx_qd(v, amax));
}

// Quantize mat[R, C] along its last dim (C), write transposed [C, R] bf16.
__global__ void quant_transpose_kernel(const float* __restrict__ in, __nv_bfloat16* __restrict__ out) {
    __shared__ __nv_bfloat16 tile[32][33];
    int lane = threadIdx.x, ty = threadIdx.y;
    int r0 = blockIdx.y * 32, c0 = blockIdx.x * 32;
    #pragma unroll
    for (int i = 0; i < 4; i++) {
        int r = ty + i * 8;
        float v = in[(size_t)(r0 + r) * DIM + c0 + lane];
        float amax = warp_amax(fabsf(v));
        tile[lane][r] = __float2bfloat16(mx_qd(v, amax));  // transposed into smem
    }
    __syncthreads();
    #pragma unroll
    for (int i = 0; i < 4; i++) {
        int r = ty + i * 8;
        out[(size_t)(c0 + r) * DIM + r0 + lane] = tile[r][lane];
    }
}

// ============================================================================
// bf16 HMMA GEMM: C[m,n] = sum_k A[m,k] * B[n,k]
//   A [M,K] K-major, B [N,K] K-major (TN), C [M,N] fp32.
//   CTA tile 128x128x64, 256 threads = 8 warps (2m x 4n), warp tile 64x32.
//   3-stage cp.async pipeline; Swizzle<3,3,3> (16B chunk XOR row&7) smem layout.
// ============================================================================
__global__ void __launch_bounds__(256, 1) gemm_bf16_kernel(
    const __nv_bfloat16* __restrict__ A,
    const __nv_bfloat16* __restrict__ B,
    float* __restrict__ C)
{
    extern __shared__ char smem[];
    const uint32_t sbase = smem_u32(smem);
    const int tid  = threadIdx.x;
    const int wid  = tid >> 5, lane = tid & 31;
    const int m0   = blockIdx.y * BM, n0 = blockIdx.x * BN;
    const int wm   = (wid >> 2) * 64;   // 0 / 64
    const int wn   = (wid & 3) * 32;    // 0 / 32 / 64 / 96

    const __nv_bfloat16* Ag = A + (size_t)m0 * DIM;
    const __nv_bfloat16* Bg = B + (size_t)n0 * DIM;

    // ---- cp.async tile issue: each thread loads 4 x 16B chunks per operand ----
    auto issue_tile = [&](int kt, int slot) {
        const int k0 = kt * BK;
        const uint32_t sA = sbase + slot * STAGE_BYTES;
        const uint32_t sB = sA + TILE_BYTES;
        #pragma unroll
        for (int i = 0; i < 4; i++) {
            int lin = tid + i * 256;
            int row = lin >> 3, c = lin & 7;
            uint32_t soff = row * 128 + ((c ^ (row & 7)) << 4);
            const void* gA = Ag + (size_t)row * DIM + k0 + c * 8;
            const void* gB = Bg + (size_t)row * DIM + k0 + c * 8;
            asm volatile("cp.async.cg.shared.global [%0], [%1], 16;" :: "r"(sA + soff), "l"(gA));
            asm volatile("cp.async.cg.shared.global [%0], [%1], 16;" :: "r"(sB + soff), "l"(gB));
        }
        asm volatile("cp.async.commit_group;" ::: "memory");
    };

    // ---- per-lane ldmatrix addressing (row & 7 == lane & 7 for all tiles) ----
    const int sw  = lane & 7;                 // swizzle XOR key
    const int ahi = lane >> 4;                // A: chunk select (k lo/hi 8)
    const int bhi = (lane >> 3) & 1;          // B: chunk select
    uint32_t aRowOff[4], bRowOff[2];
    #pragma unroll
    for (int mi = 0; mi < 4; mi++)
        aRowOff[mi] = (wm + mi * 16 + (lane & 7) + ((lane >> 3) & 1) * 8) * 128;
    #pragma unroll
    for (int nj = 0; nj < 2; nj++)
        bRowOff[nj] = (wn + nj * 16 + (lane & 7) + (lane >> 4) * 8) * 128;

    float acc[4][4][4];
    #pragma unroll
    for (int mi = 0; mi < 4; mi++)
        #pragma unroll
        for (int ni = 0; ni < 4; ni++)
            #pragma unroll
            for (int j = 0; j < 4; j++) acc[mi][ni][j] = 0.0f;

    // ---- pipeline prologue ----
    issue_tile(0, 0);
    issue_tile(1, 1);

    for (int kt = 0; kt < NKITER; kt++) {
        asm volatile("cp.async.wait_group 1;" ::: "memory");  // tile kt resident
        __syncthreads();

        const int knext = kt + 2;
        if (knext < NKITER) issue_tile(knext, knext % STAGES);
        else asm volatile("cp.async.commit_group;" ::: "memory");  // keep group count

        const uint32_t sA = sbase + (kt % STAGES) * STAGE_BYTES;
        const uint32_t sB = sA + TILE_BYTES;

        #pragma unroll
        for (int ks = 0; ks < BK / 16; ks++) {
            const uint32_t a_c = (uint32_t)(((ks * 2 + ahi) ^ sw) << 4);
            const uint32_t b_c = (uint32_t)(((ks * 2 + bhi) ^ sw) << 4);
            uint32_t afr[4][4], bfr[2][4];
            #pragma unroll
            for (int mi = 0; mi < 4; mi++) ldmatrix_x4(afr[mi], sA + aRowOff[mi] + a_c);
            #pragma unroll
            for (int nj = 0; nj < 2; nj++) ldmatrix_x4(bfr[nj], sB + bRowOff[nj] + b_c);
            #pragma unroll
            for (int mi = 0; mi < 4; mi++)
                #pragma unroll
                for (int ni = 0; ni < 4; ni++)
                    mma_16816(acc[mi][ni], afr[mi],
                              bfr[ni >> 1][(ni & 1) * 2], bfr[ni >> 1][(ni & 1) * 2 + 1]);
        }
    }

    // ---- epilogue: fp32 stores (mma c-frag layout) ----
    const int tr = lane >> 2, tc = (lane & 3) * 2;
    #pragma unroll
    for (int mi = 0; mi < 4; mi++) {
        const int m = m0 + wm + mi * 16 + tr;
        #pragma unroll
        for (int ni = 0; ni < 4; ni++) {
            const int n = n0 + wn + ni * 8 + tc;
            float2* p0 = reinterpret_cast<float2*>(C + (size_t)m * DIM + n);
            float2* p1 = reinterpret_cast<float2*>(C + (size_t)(m + 8) * DIM + n);
            *p0 = make_float2(acc[mi][ni][0], acc[mi][ni][1]);
            *p1 = make_float2(acc[mi][ni][2], acc[mi][ni][3]);
        }
    }
}

// ============================================================================
// Host side
// ============================================================================
extern "C" void kernel_launch(void* const* d_in, const int* in_sizes, int n_in,
                              void* d_out, int out_size) {
    const float* x_mx = (const float*)d_in[0];
    const float* mat1 = (const float*)d_in[1];
    const float* mat2 = (const float*)d_in[2];
    float* out = (float*)d_out;

    void *pX, *pW1T, *pW2T, *pH, *pH2;
    cudaGetSymbolAddress(&pX,   g_X);
    cudaGetSymbolAddress(&pW1T, g_W1T);
    cudaGetSymbolAddress(&pW2T, g_W2T);
    cudaGetSymbolAddress(&pH,   g_H);
    cudaGetSymbolAddress(&pH2,  g_H2);

    cudaFuncSetAttribute(gemm_bf16_kernel,
                         cudaFuncAttributeMaxDynamicSharedMemorySize, SMEM_TOTAL);

    dim3 tgrid(DIM / 32, DIM / 32), tblk(32, 8);
    dim3 ggrid(DIM / BN, DIM / BM);

    // 1-3: quantize inputs (x kept row-layout; mat1/mat2 transposed to K-major)
    quant_rows_kernel<<<(unsigned)(NELEM / 256), 256>>>(x_mx, (__nv_bfloat16*)pX);
    quant_transpose_kernel<<<tgrid, tblk>>>(mat1, (__nv_bfloat16*)pW1T);
    quant_transpose_kernel<<<tgrid, tblk>>>(mat2, (__nv_bfloat16*)pW2T);

    // 4: H = Xq @ W1q^T (fp32)
    gemm_bf16_kernel<<<ggrid, 256, SMEM_TOTAL>>>(
        (const __nv_bfloat16*)pX, (const __nv_bfloat16*)pW1T, (float*)pH);

    // 5: requantize intermediate along its last dim
    quant_rows_kernel<<<(unsigned)(NELEM / 256), 256>>>((const float*)pH, (__nv_bfloat16*)pH2);

    // 6: out = H2q @ W2q^T
    gemm_bf16_kernel<<<ggrid, 256, SMEM_TOTAL>>>(
        (const __nv_bfloat16*)pH2, (const __nv_bfloat16*)pW2T, out);
}

// round 3
// speedup vs baseline: 1.1349x; 1.1349x over previous
#include <cuda_runtime.h>
#include <cuda_bf16.h>
#include <cuda_fp8.h>
#include <cstdint>
#include <cstddef>

// ============================================================================
// Problem constants
// ============================================================================
#define DIM 4096
#define NELEM ((size_t)DIM * (size_t)DIM)

// GEMM tiling
#define BM 128
#define BN 128
#define BK 64                        // 64 bf16 = 128 bytes per smem row
#define NKITER (DIM / BK)            // 64
#define STAGES 4
#define TILE_BYTES (BM * BK * 2)     // 16 KB per operand tile
#define STAGE_BYTES (2 * TILE_BYTES) // 32 KB (A + B)
#define SMEM_TOTAL (STAGES * STAGE_BYTES)  // 128 KB

// ============================================================================
// Scratch (device globals — no allocations allowed)
// ============================================================================
__device__ __align__(1024) __nv_bfloat16 g_X  [NELEM];  // quantized x       [M,K] K-major
__device__ __align__(1024) __nv_bfloat16 g_W1T[NELEM];  // quantized mat1^T  [N,K] K-major
__device__ __align__(1024) __nv_bfloat16 g_W2T[NELEM];  // quantized mat2^T  [N,K] K-major
__device__ __align__(1024) __nv_bfloat16 g_H2 [NELEM];  // requantized GEMM1 out [M,K] K-major

// ============================================================================
// Helpers
// ============================================================================
__device__ __forceinline__ uint32_t smem_u32(const void* p) {
    uint32_t a;
    asm("{ .reg .u64 t; cvta.to.shared.u64 t, %1; cvt.u32.u64 %0, t; }" : "=r"(a) : "l"(p));
    return a;
}

__device__ __forceinline__ void ldmatrix_x4(uint32_t* r, uint32_t addr) {
    asm volatile("ldmatrix.sync.aligned.m8n8.x4.shared.b16 {%0,%1,%2,%3}, [%4];"
                 : "=r"(r[0]), "=r"(r[1]), "=r"(r[2]), "=r"(r[3]) : "r"(addr));
}

__device__ __forceinline__ void mma_16816(float* c, const uint32_t* a, uint32_t b0, uint32_t b1) {
    asm volatile(
        "mma.sync.aligned.m16n8k16.row.col.f32.bf16.bf16.f32 "
        "{%0,%1,%2,%3}, {%4,%5,%6,%7}, {%8,%9}, {%0,%1,%2,%3};"
        : "+f"(c[0]), "+f"(c[1]), "+f"(c[2]), "+f"(c[3])
        : "r"(a[0]), "r"(a[1]), "r"(a[2]), "r"(a[3]), "r"(b0), "r"(b1));
}

// ============================================================================
// MX quant-dequant (exact match of the reference semantics)
// ============================================================================
__device__ __forceinline__ float mx_qd(float v, float amax) {
    if (amax == 0.0f) return 0.0f;              // all-zero block
    int e;
    frexpf(amax, &e);                           // amax = m * 2^e, m in [0.5,1)
    int se = (e - 1) - 8;                       // floor(log2(amax)) - 8 (exact)
    se = max(-127, min(127, se));
    float vs = ldexpf(v, -se);                  // v / 2^se, exact
    __nv_fp8_storage_t q = __nv_cvt_float_to_fp8(vs, __NV_SATFINITE, __NV_E4M3);
    __half_raw hr = __nv_cvt_fp8_to_halfraw(q, __NV_E4M3);
    return ldexpf(__half2float(*reinterpret_cast<__half*>(&hr)), se);
}

// ============================================================================
// Vectorized quantize along contiguous dim: 8 lanes x float4 = one 32-block.
// ============================================================================
__global__ void quant_rows_v4(const float4* __restrict__ in, uint2* __restrict__ out) {
    size_t idx = (size_t)blockIdx.x * blockDim.x + threadIdx.x;
    float4 v = in[idx];
    float a = fmaxf(fmaxf(fabsf(v.x), fabsf(v.y)), fmaxf(fabsf(v.z), fabsf(v.w)));
    #pragma unroll
    for (int off = 4; off >= 1; off >>= 1)
        a = fmaxf(a, __shfl_xor_sync(0xFFFFFFFFu, a, off, 8));
    __nv_bfloat16 q0 = __float2bfloat16(mx_qd(v.x, a));
    __nv_bfloat16 q1 = __float2bfloat16(mx_qd(v.y, a));
    __nv_bfloat16 q2 = __float2bfloat16(mx_qd(v.z, a));
    __nv_bfloat16 q3 = __float2bfloat16(mx_qd(v.w, a));
    uint2 o;
    o.x = ((uint32_t)__bfloat16_as_ushort(q1) << 16) | __bfloat16_as_ushort(q0);
    o.y = ((uint32_t)__bfloat16_as_ushort(q3) << 16) | __bfloat16_as_ushort(q2);
    out[idx] = o;
}

// Quantize mat[R, C] along last dim (C, blocks of 32), write transposed [C, R] bf16.
// 256 threads; 32x32 tile. Load: float4 per thread (8 lanes per row). Store: uint2.
__global__ void quant_transpose_v4(const float* __restrict__ in, __nv_bfloat16* __restrict__ out) {
    __shared__ __nv_bfloat16 tile[32][36];   // [c][r], padded (72B rows, 8B aligned)
    const int tid = threadIdx.x;
    const int r0 = blockIdx.y * 32, c0 = blockIdx.x * 32;
    {
        const int r = tid >> 3, cg = tid & 7;
        float4 v = *reinterpret_cast<const float4*>(in + (size_t)(r0 + r) * DIM + c0 + cg * 4);
        float a = fmaxf(fmaxf(fabsf(v.x), fabsf(v.y)), fmaxf(fabsf(v.z), fabsf(v.w)));
        #pragma unroll
        for (int off = 4; off >= 1; off >>= 1)
            a = fmaxf(a, __shfl_xor_sync(0xFFFFFFFFu, a, off, 8));
        tile[cg * 4 + 0][r] = __float2bfloat16(mx_qd(v.x, a));
        tile[cg * 4 + 1][r] = __float2bfloat16(mx_qd(v.y, a));
        tile[cg * 4 + 2][r] = __float2bfloat16(mx_qd(v.z, a));
        tile[cg * 4 + 3][r] = __float2bfloat16(mx_qd(v.w, a));
    }
    __syncthreads();
    {
        const int c = tid >> 3, rg = tid & 7;
        uint2 o = *reinterpret_cast<const uint2*>(&tile[c][rg * 4]);
        *reinterpret_cast<uint2*>(out + (size_t)(c0 + c) * DIM + r0 + rg * 4) = o;
    }
}

// ============================================================================
// bf16 HMMA GEMM: C[m,n] = sum_k A[m,k] * B[n,k]
//   A [M,K] K-major, B [N,K] K-major (TN), C [M,N].
//   CTA 128x128x64, 256 threads = 8 warps (2m x 4n), warp tile 64x32.
//   4-stage cp.async pipeline (wait_group 2); frag double-buffering;
//   Swizzle<3,3,3> smem layout.
//   REQUANT: fused MX requantize along N (warp tile N==32 == one MX block),
//   writes bf16; else writes fp32.
// ============================================================================
template <bool REQUANT>
__global__ void __launch_bounds__(256, 1) gemm_bf16_kernel(
    const __nv_bfloat16* __restrict__ A,
    const __nv_bfloat16* __restrict__ B,
    void* __restrict__ Cout)
{
    extern __shared__ char smem[];
    const uint32_t sbase = smem_u32(smem);
    const int tid  = threadIdx.x;
    const int wid  = tid >> 5, lane = tid & 31;
    const int m0   = blockIdx.y * BM, n0 = blockIdx.x * BN;
    const int wm   = (wid >> 2) * 64;   // 0 / 64
    const int wn   = (wid & 3) * 32;    // 0 / 32 / 64 / 96

    const __nv_bfloat16* Ag = A + (size_t)m0 * DIM;
    const __nv_bfloat16* Bg = B + (size_t)n0 * DIM;

    // ---- cp.async tile issue: each thread loads 4 x 16B chunks per operand ----
    auto issue_tile = [&](int kt, int slot) {
        const int k0 = kt * BK;
        const uint32_t sA = sbase + slot * STAGE_BYTES;
        const uint32_t sB = sA + TILE_BYTES;
        #pragma unroll
        for (int i = 0; i < 4; i++) {
            int lin = tid + i * 256;
            int row = lin >> 3, c = lin & 7;
            uint32_t soff = row * 128 + ((c ^ (row & 7)) << 4);
            const void* gA = Ag + (size_t)row * DIM + k0 + c * 8;
            const void* gB = Bg + (size_t)row * DIM + k0 + c * 8;
            asm volatile("cp.async.cg.shared.global [%0], [%1], 16;" :: "r"(sA + soff), "l"(gA));
            asm volatile("cp.async.cg.shared.global [%0], [%1], 16;" :: "r"(sB + soff), "l"(gB));
        }
        asm volatile("cp.async.commit_group;" ::: "memory");
    };

    // ---- per-lane ldmatrix addressing ----
    const int sw  = lane & 7;                 // swizzle XOR key
    const int ahi = lane >> 4;                // A: chunk select
    const int bhi = (lane >> 3) & 1;          // B: chunk select
    uint32_t aRowOff[4], bRowOff[2];
    #pragma unroll
    for (int mi = 0; mi < 4; mi++)
        aRowOff[mi] = (wm + mi * 16 + (lane & 7) + ((lane >> 3) & 1) * 8) * 128;
    #pragma unroll
    for (int nj = 0; nj < 2; nj++)
        bRowOff[nj] = (wn + nj * 16 + (lane & 7) + (lane >> 4) * 8) * 128;

    auto load_frags = [&](uint32_t sA, uint32_t sB, uint32_t (*af)[4], uint32_t (*bf)[4], int ks) {
        const uint32_t a_c = (uint32_t)(((ks * 2 + ahi) ^ sw) << 4);
        const uint32_t b_c = (uint32_t)(((ks * 2 + bhi) ^ sw) << 4);
        #pragma unroll
        for (int mi = 0; mi < 4; mi++) ldmatrix_x4(af[mi], sA + aRowOff[mi] + a_c);
        #pragma unroll
        for (int nj = 0; nj < 2; nj++) ldmatrix_x4(bf[nj], sB + bRowOff[nj] + b_c);
    };

    float acc[4][4][4];
    #pragma unroll
    for (int mi = 0; mi < 4; mi++)
        #pragma unroll
        for (int ni = 0; ni < 4; ni++)
            #pragma unroll
            for (int j = 0; j < 4; j++) acc[mi][ni][j] = 0.0f;

    // ---- pipeline prologue: fill 3 of 4 stages ----
    issue_tile(0, 0);
    issue_tile(1, 1);
    issue_tile(2, 2);

    uint32_t afr[2][4][4], bfr[2][2][4];

    for (int kt = 0; kt < NKITER; kt++) {
        asm volatile("cp.async.wait_group 2;" ::: "memory");  // tile kt resident
        __syncthreads();

        const int knext = kt + 3;
        if (knext < NKITER) issue_tile(knext, knext % STAGES);
        else asm volatile("cp.async.commit_group;" ::: "memory");  // keep group count

        const uint32_t sA = sbase + (kt % STAGES) * STAGE_BYTES;
        const uint32_t sB = sA + TILE_BYTES;

        load_frags(sA, sB, afr[0], bfr[0], 0);
        #pragma unroll
        for (int ks = 0; ks < BK / 16; ks++) {
            const int cur = ks & 1;
            if (ks < BK / 16 - 1)
                load_frags(sA, sB, afr[cur ^ 1], bfr[cur ^ 1], ks + 1);
            #pragma unroll
            for (int mi = 0; mi < 4; mi++)
                #pragma unroll
                for (int ni = 0; ni < 4; ni++)
                    mma_16816(acc[mi][ni], afr[cur][mi],
                              bfr[cur][ni >> 1][(ni & 1) * 2], bfr[cur][ni >> 1][(ni & 1) * 2 + 1]);
        }
    }

    // ---- epilogue ----
    const int tr = lane >> 2, tc = (lane & 3) * 2;
    if (!REQUANT) {
        float* C = (float*)Cout;
        #pragma unroll
        for (int mi = 0; mi < 4; mi++) {
            const int m = m0 + wm + mi * 16 + tr;
            #pragma unroll
            for (int ni = 0; ni < 4; ni++) {
                const int n = n0 + wn + ni * 8 + tc;
                *reinterpret_cast<float2*>(C + (size_t)m * DIM + n) =
                    make_float2(acc[mi][ni][0], acc[mi][ni][1]);
                *reinterpret_cast<float2*>(C + (size_t)(m + 8) * DIM + n) =
                    make_float2(acc[mi][ni][2], acc[mi][ni][3]);
            }
        }
    } else {
        // Warp's N-range [n0+wn, n0+wn+32) is exactly one MX block per row.
        // Row r (tr) values live in lanes sharing tr (groups of 4) x ni x j pairs.
        __nv_bfloat16* C = (__nv_bfloat16*)Cout;
        #pragma unroll
        for (int mi = 0; mi < 4; mi++) {
            #pragma unroll
            for (int h = 0; h < 2; h++) {          // row tr  /  row tr+8
                float a = 0.0f;
                #pragma unroll
                for (int ni = 0; ni < 4; ni++)
                    a = fmaxf(a, fmaxf(fabsf(acc[mi][ni][2 * h]), fabsf(acc[mi][ni][2 * h + 1])));
                a = fmaxf(a, __shfl_xor_sync(0xFFFFFFFFu, a, 1, 4));
                a = fmaxf(a, __shfl_xor_sync(0xFFFFFFFFu, a, 2, 4));
                const int m = m0 + wm + mi * 16 + h * 8 + tr;
                #pragma unroll
                for (int ni = 0; ni < 4; ni++) {
                    const int n = n0 + wn + ni * 8 + tc;
                    __nv_bfloat16 q0 = __float2bfloat16(mx_qd(acc[mi][ni][2 * h], a));
                    __nv_bfloat16 q1 = __float2bfloat16(mx_qd(acc[mi][ni][2 * h + 1], a));
                    uint32_t pk = ((uint32_t)__bfloat16_as_ushort(q1) << 16) |
                                  __bfloat16_as_ushort(q0);
                    *reinterpret_cast<uint32_t*>(C + (size_t)m * DIM + n) = pk;
                }
            }
        }
    }
}

// ============================================================================
// Host side
// ============================================================================
extern "C" void kernel_launch(void* const* d_in, const int* in_sizes, int n_in,
                              void* d_out, int out_size) {
    const float* x_mx = (const float*)d_in[0];
    const float* mat1 = (const float*)d_in[1];
    const float* mat2 = (const float*)d_in[2];
    float* out = (float*)d_out;

    void *pX, *pW1T, *pW2T, *pH2;
    cudaGetSymbolAddress(&pX,   g_X);
    cudaGetSymbolAddress(&pW1T, g_W1T);
    cudaGetSymbolAddress(&pW2T, g_W2T);
    cudaGetSymbolAddress(&pH2,  g_H2);

    cudaFuncSetAttribute(gemm_bf16_kernel<false>,
                         cudaFuncAttributeMaxDynamicSharedMemorySize, SMEM_TOTAL);
    cudaFuncSetAttribute(gemm_bf16_kernel<true>,
                         cudaFuncAttributeMaxDynamicSharedMemorySize, SMEM_TOTAL);

    dim3 tgrid(DIM / 32, DIM / 32);
    dim3 ggrid(DIM / BN, DIM / BM);

    // 1-3: quantize inputs (x kept row-layout; mat1/mat2 transposed to K-major)
    quant_rows_v4<<<(unsigned)(NELEM / 1024), 256>>>((const float4*)x_mx, (uint2*)pX);
    quant_transpose_v4<<<tgrid, 256>>>(mat1, (__nv_bfloat16*)pW1T);
    quant_transpose_v4<<<tgrid, 256>>>(mat2, (__nv_bfloat16*)pW2T);

    // 4: H2 = requant(Xq @ W1q^T)  — requant fused into the epilogue
    gemm_bf16_kernel<true><<<ggrid, 256, SMEM_TOTAL>>>(
        (const __nv_bfloat16*)pX, (const __nv_bfloat16*)pW1T, pH2);

    // 5: out = H2q @ W2q^T
    gemm_bf16_kernel<false><<<ggrid, 256, SMEM_TOTAL>>>(
        (const __nv_bfloat16*)pH2, (const __nv_bfloat16*)pW2T, out);
}

// round 4
// speedup vs baseline: 1.3181x; 1.1614x over previous
#include <cuda_runtime.h>
#include <cuda_bf16.h>
#include <cuda_fp8.h>
#include <cstdint>
#include <cstddef>

// ============================================================================
// Problem constants
// ============================================================================
#define DIM 4096
#define NELEM ((size_t)DIM * (size_t)DIM)

// GEMM tiling
#define BM 128
#define BN 128
#define BK 64                        // 64 bf16 = 128 bytes per smem row
#define NKITER (DIM / BK)            // 64
#define STAGES 3
#define TILE_BYTES (BM * BK * 2)     // 16 KB per operand tile
#define STAGE_BYTES (2 * TILE_BYTES) // 32 KB (A + B)
#define SMEM_TOTAL (STAGES * STAGE_BYTES)  // 96 KB -> 2 CTAs / SM

// ============================================================================
// Scratch (device globals — no allocations allowed)
// ============================================================================
__device__ __align__(1024) __nv_bfloat16 g_X  [NELEM];  // quantized x       [M,K] K-major
__device__ __align__(1024) __nv_bfloat16 g_W1T[NELEM];  // quantized mat1^T  [N,K] K-major
__device__ __align__(1024) __nv_bfloat16 g_W2T[NELEM];  // quantized mat2^T  [N,K] K-major
__device__ __align__(1024) __nv_bfloat16 g_H2 [NELEM];  // requantized GEMM1 out [M,K] K-major

// ============================================================================
// Helpers
// ============================================================================
__device__ __forceinline__ uint32_t smem_u32(const void* p) {
    uint32_t a;
    asm("{ .reg .u64 t; cvta.to.shared.u64 t, %1; cvt.u32.u64 %0, t; }" : "=r"(a) : "l"(p));
    return a;
}

__device__ __forceinline__ void ldmatrix_x4(uint32_t* r, uint32_t addr) {
    asm volatile("ldmatrix.sync.aligned.m8n8.x4.shared.b16 {%0,%1,%2,%3}, [%4];"
                 : "=r"(r[0]), "=r"(r[1]), "=r"(r[2]), "=r"(r[3]) : "r"(addr));
}

__device__ __forceinline__ void mma_16816(float* c, const uint32_t* a, uint32_t b0, uint32_t b1) {
    asm volatile(
        "mma.sync.aligned.m16n8k16.row.col.f32.bf16.bf16.f32 "
        "{%0,%1,%2,%3}, {%4,%5,%6,%7}, {%8,%9}, {%0,%1,%2,%3};"
        : "+f"(c[0]), "+f"(c[1]), "+f"(c[2]), "+f"(c[3])
        : "r"(a[0]), "r"(a[1]), "r"(a[2]), "r"(a[3]), "r"(b0), "r"(b1));
}

// ============================================================================
// MX quant-dequant (exact match of the reference semantics)
// ============================================================================
__device__ __forceinline__ float mx_qd(float v, float amax) {
    if (amax == 0.0f) return 0.0f;              // all-zero block
    int e;
    frexpf(amax, &e);                           // amax = m * 2^e, m in [0.5,1)
    int se = (e - 1) - 8;                       // floor(log2(amax)) - 8 (exact)
    se = max(-127, min(127, se));
    float vs = ldexpf(v, -se);                  // v / 2^se, exact
    __nv_fp8_storage_t q = __nv_cvt_float_to_fp8(vs, __NV_SATFINITE, __NV_E4M3);
    __half_raw hr = __nv_cvt_fp8_to_halfraw(q, __NV_E4M3);
    return ldexpf(__half2float(*reinterpret_cast<__half*>(&hr)), se);
}

// ============================================================================
// Vectorized quantize along contiguous dim: 8 lanes x float4 = one 32-block.
// ============================================================================
__global__ void quant_rows_v4(const float4* __restrict__ in, uint2* __restrict__ out) {
    size_t idx = (size_t)blockIdx.x * blockDim.x + threadIdx.x;
    float4 v = in[idx];
    float a = fmaxf(fmaxf(fabsf(v.x), fabsf(v.y)), fmaxf(fabsf(v.z), fabsf(v.w)));
    #pragma unroll
    for (int off = 4; off >= 1; off >>= 1)
        a = fmaxf(a, __shfl_xor_sync(0xFFFFFFFFu, a, off, 8));
    __nv_bfloat16 q0 = __float2bfloat16(mx_qd(v.x, a));
    __nv_bfloat16 q1 = __float2bfloat16(mx_qd(v.y, a));
    __nv_bfloat16 q2 = __float2bfloat16(mx_qd(v.z, a));
    __nv_bfloat16 q3 = __float2bfloat16(mx_qd(v.w, a));
    uint2 o;
    o.x = ((uint32_t)__bfloat16_as_ushort(q1) << 16) | __bfloat16_as_ushort(q0);
    o.y = ((uint32_t)__bfloat16_as_ushort(q3) << 16) | __bfloat16_as_ushort(q2);
    out[idx] = o;
}

// Quantize mat[R, C] along last dim (C, blocks of 32), write transposed [C, R] bf16.
__global__ void quant_transpose_v4(const float* __restrict__ in, __nv_bfloat16* __restrict__ out) {
    __shared__ __nv_bfloat16 tile[32][36];   // [c][r], padded
    const int tid = threadIdx.x;
    const int r0 = blockIdx.y * 32, c0 = blockIdx.x * 32;
    {
        const int r = tid >> 3, cg = tid & 7;
        float4 v = *reinterpret_cast<const float4*>(in + (size_t)(r0 + r) * DIM + c0 + cg * 4);
        float a = fmaxf(fmaxf(fabsf(v.x), fabsf(v.y)), fmaxf(fabsf(v.z), fabsf(v.w)));
        #pragma unroll
        for (int off = 4; off >= 1; off >>= 1)
            a = fmaxf(a, __shfl_xor_sync(0xFFFFFFFFu, a, off, 8));
        tile[cg * 4 + 0][r] = __float2bfloat16(mx_qd(v.x, a));
        tile[cg * 4 + 1][r] = __float2bfloat16(mx_qd(v.y, a));
        tile[cg * 4 + 2][r] = __float2bfloat16(mx_qd(v.z, a));
        tile[cg * 4 + 3][r] = __float2bfloat16(mx_qd(v.w, a));
    }
    __syncthreads();
    {
        const int c = tid >> 3, rg = tid & 7;
        uint2 o = *reinterpret_cast<const uint2*>(&tile[c][rg * 4]);
        *reinterpret_cast<uint2*>(out + (size_t)(c0 + c) * DIM + r0 + rg * 4) = o;
    }
}

// ============================================================================
// bf16 HMMA GEMM: C[m,n] = sum_k A[m,k] * B[n,k]
//   CTA 128x128x64, 256 threads = 8 warps (2m x 4n), warp tile 64x32.
//   3-stage cp.async pipeline; single-buffer frags; 2 CTAs / SM.
// ============================================================================
template <bool REQUANT>
__global__ void __launch_bounds__(256, 2) gemm_bf16_kernel(
    const __nv_bfloat16* __restrict__ A,
    const __nv_bfloat16* __restrict__ B,
    void* __restrict__ Cout)
{
    extern __shared__ char smem[];
    const uint32_t sbase = smem_u32(smem);
    const int tid  = threadIdx.x;
    const int wid  = tid >> 5, lane = tid & 31;
    const int m0   = blockIdx.y * BM, n0 = blockIdx.x * BN;
    const int wm   = (wid >> 2) * 64;   // 0 / 64
    const int wn   = (wid & 3) * 32;    // 0 / 32 / 64 / 96

    const __nv_bfloat16* Ag = A + (size_t)m0 * DIM;
    const __nv_bfloat16* Bg = B + (size_t)n0 * DIM;

    // ---- cp.async tile issue: each thread loads 4 x 16B chunks per operand ----
    auto issue_tile = [&](int kt, int slot) {
        const int k0 = kt * BK;
        const uint32_t sA = sbase + slot * STAGE_BYTES;
        const uint32_t sB = sA + TILE_BYTES;
        #pragma unroll
        for (int i = 0; i < 4; i++) {
            int lin = tid + i * 256;
            int row = lin >> 3, c = lin & 7;
            uint32_t soff = row * 128 + ((c ^ (row & 7)) << 4);
            const void* gA = Ag + (size_t)row * DIM + k0 + c * 8;
            const void* gB = Bg + (size_t)row * DIM + k0 + c * 8;
            asm volatile("cp.async.cg.shared.global [%0], [%1], 16;" :: "r"(sA + soff), "l"(gA));
            asm volatile("cp.async.cg.shared.global [%0], [%1], 16;" :: "r"(sB + soff), "l"(gB));
        }
        asm volatile("cp.async.commit_group;" ::: "memory");
    };

    // ---- per-lane ldmatrix addressing ----
    const int sw  = lane & 7;                 // swizzle XOR key
    const int ahi = lane >> 4;                // A: chunk select
    const int bhi = (lane >> 3) & 1;          // B: chunk select
    uint32_t aRowOff[4], bRowOff[2];
    #pragma unroll
    for (int mi = 0; mi < 4; mi++)
        aRowOff[mi] = (wm + mi * 16 + (lane & 7) + ((lane >> 3) & 1) * 8) * 128;
    #pragma unroll
    for (int nj = 0; nj < 2; nj++)
        bRowOff[nj] = (wn + nj * 16 + (lane & 7) + (lane >> 4) * 8) * 128;

    float acc[4][4][4];
    #pragma unroll
    for (int mi = 0; mi < 4; mi++)
        #pragma unroll
        for (int ni = 0; ni < 4; ni++)
            #pragma unroll
            for (int j = 0; j < 4; j++) acc[mi][ni][j] = 0.0f;

    // ---- pipeline prologue: fill 2 of 3 stages ----
    issue_tile(0, 0);
    issue_tile(1, 1);

    for (int kt = 0; kt < NKITER; kt++) {
        asm volatile("cp.async.wait_group 1;" ::: "memory");  // tile kt resident
        __syncthreads();

        const int knext = kt + 2;
        if (knext < NKITER) issue_tile(knext, knext % STAGES);
        else asm volatile("cp.async.commit_group;" ::: "memory");  // keep group count

        const uint32_t sA = sbase + (kt % STAGES) * STAGE_BYTES;
        const uint32_t sB = sA + TILE_BYTES;

        #pragma unroll
        for (int ks = 0; ks < BK / 16; ks++) {
            const uint32_t a_c = (uint32_t)(((ks * 2 + ahi) ^ sw) << 4);
            const uint32_t b_c = (uint32_t)(((ks * 2 + bhi) ^ sw) << 4);
            uint32_t afr[4][4], bfr[2][4];
            #pragma unroll
            for (int mi = 0; mi < 4; mi++) ldmatrix_x4(afr[mi], sA + aRowOff[mi] + a_c);
            #pragma unroll
            for (int nj = 0; nj < 2; nj++) ldmatrix_x4(bfr[nj], sB + bRowOff[nj] + b_c);
            #pragma unroll
            for (int mi = 0; mi < 4; mi++)
                #pragma unroll
                for (int ni = 0; ni < 4; ni++)
                    mma_16816(acc[mi][ni], afr[mi],
                              bfr[ni >> 1][(ni & 1) * 2], bfr[ni >> 1][(ni & 1) * 2 + 1]);
        }
    }

    // ---- epilogue ----
    const int tr = lane >> 2, tc = (lane & 3) * 2;
    if (!REQUANT) {
        float* C = (float*)Cout;
        #pragma unroll
        for (int mi = 0; mi < 4; mi++) {
            const int m = m0 + wm + mi * 16 + tr;
            #pragma unroll
            for (int ni = 0; ni < 4; ni++) {
                const int n = n0 + wn + ni * 8 + tc;
                *reinterpret_cast<float2*>(C + (size_t)m * DIM + n) =
                    make_float2(acc[mi][ni][0], acc[mi][ni][1]);
                *reinterpret_cast<float2*>(C + (size_t)(m + 8) * DIM + n) =
                    make_float2(acc[mi][ni][2], acc[mi][ni][3]);
            }
        }
    } else {
        // Warp's N-range [n0+wn, n0+wn+32) is exactly one MX block per row.
        __nv_bfloat16* C = (__nv_bfloat16*)Cout;
        #pragma unroll
        for (int mi = 0; mi < 4; mi++) {
            #pragma unroll
            for (int h = 0; h < 2; h++) {          // row tr  /  row tr+8
                float a = 0.0f;
                #pragma unroll
                for (int ni = 0; ni < 4; ni++)
                    a = fmaxf(a, fmaxf(fabsf(acc[mi][ni][2 * h]), fabsf(acc[mi][ni][2 * h + 1])));
                a = fmaxf(a, __shfl_xor_sync(0xFFFFFFFFu, a, 1, 4));
                a = fmaxf(a, __shfl_xor_sync(0xFFFFFFFFu, a, 2, 4));
                const int m = m0 + wm + mi * 16 + h * 8 + tr;
                #pragma unroll
                for (int ni = 0; ni < 4; ni++) {
                    const int n = n0 + wn + ni * 8 + tc;
                    __nv_bfloat16 q0 = __float2bfloat16(mx_qd(acc[mi][ni][2 * h], a));
                    __nv_bfloat16 q1 = __float2bfloat16(mx_qd(acc[mi][ni][2 * h + 1], a));
                    uint32_t pk = ((uint32_t)__bfloat16_as_ushort(q1) << 16) |
                                  __bfloat16_as_ushort(q0);
                    *reinterpret_cast<uint32_t*>(C + (size_t)m * DIM + n) = pk;
                }
            }
        }
    }
}

// ============================================================================
// Host side
// ============================================================================
extern "C" void kernel_launch(void* const* d_in, const int* in_sizes, int n_in,
                              void* d_out, int out_size) {
    const float* x_mx = (const float*)d_in[0];
    const float* mat1 = (const float*)d_in[1];
    const float* mat2 = (const float*)d_in[2];
    float* out = (float*)d_out;

    void *pX, *pW1T, *pW2T, *pH2;
    cudaGetSymbolAddress(&pX,   g_X);
    cudaGetSymbolAddress(&pW1T, g_W1T);
    cudaGetSymbolAddress(&pW2T, g_W2T);
    cudaGetSymbolAddress(&pH2,  g_H2);

    cudaFuncSetAttribute(gemm_bf16_kernel<false>,
                         cudaFuncAttributeMaxDynamicSharedMemorySize, SMEM_TOTAL);
    cudaFuncSetAttribute(gemm_bf16_kernel<true>,
                         cudaFuncAttributeMaxDynamicSharedMemorySize, SMEM_TOTAL);

    dim3 tgrid(DIM / 32, DIM / 32);
    dim3 ggrid(DIM / BN, DIM / BM);

    // 1-3: quantize inputs (x kept row-layout; mat1/mat2 transposed to K-major)
    quant_rows_v4<<<(unsigned)(NELEM / 1024), 256>>>((const float4*)x_mx, (uint2*)pX);
    quant_transpose_v4<<<tgrid, 256>>>(mat1, (__nv_bfloat16*)pW1T);
    quant_transpose_v4<<<tgrid, 256>>>(mat2, (__nv_bfloat16*)pW2T);

    // 4: H2 = requant(Xq @ W1q^T)  — requant fused into the epilogue
    gemm_bf16_kernel<true><<<ggrid, 256, SMEM_TOTAL>>>(
        (const __nv_bfloat16*)pX, (const __nv_bfloat16*)pW1T, pH2);

    // 5: out = H2q @ W2q^T
    gemm_bf16_kernel<false><<<ggrid, 256, SMEM_TOTAL>>>(
        (const __nv_bfloat16*)pH2, (const __nv_bfloat16*)pW2T, out);
}

// round 5
// speedup vs baseline: 1.3626x; 1.0337x over previous
#include <cuda_runtime.h>
#include <cuda_bf16.h>
#include <cuda_fp8.h>
#include <cstdint>
#include <cstddef>

// ============================================================================
// Problem constants
// ============================================================================
#define DIM 4096
#define NELEM ((size_t)DIM * (size_t)DIM)

// GEMM tiling
#define BM 128
#define BN 128
#define BK 64                        // 64 bf16 = 128 bytes per smem row
#define NKITER (DIM / BK)            // 64
#define STAGES 3
#define TILE_BYTES (BM * BK * 2)     // 16 KB per operand tile
#define STAGE_BYTES (2 * TILE_BYTES) // 32 KB (A + B)
#define SMEM_TOTAL (STAGES * STAGE_BYTES)  // 96 KB -> 2 CTAs / SM
#define BK_BYTES (BK * 2)

// ============================================================================
// Scratch (device globals — no allocations allowed)
// ============================================================================
__device__ __align__(1024) __nv_bfloat16 g_X  [NELEM];  // quantized x       [M,K] K-major
__device__ __align__(1024) __nv_bfloat16 g_W1T[NELEM];  // quantized mat1^T  [N,K] K-major
__device__ __align__(1024) __nv_bfloat16 g_W2T[NELEM];  // quantized mat2^T  [N,K] K-major
__device__ __align__(1024) __nv_bfloat16 g_H2 [NELEM];  // requantized GEMM1 out [M,K] K-major

// ============================================================================
// Helpers
// ============================================================================
__device__ __forceinline__ uint32_t smem_u32(const void* p) {
    uint32_t a;
    asm("{ .reg .u64 t; cvta.to.shared.u64 t, %1; cvt.u32.u64 %0, t; }" : "=r"(a) : "l"(p));
    return a;
}

__device__ __forceinline__ void ldmatrix_x4(uint32_t* r, uint32_t addr) {
    asm volatile("ldmatrix.sync.aligned.m8n8.x4.shared.b16 {%0,%1,%2,%3}, [%4];"
                 : "=r"(r[0]), "=r"(r[1]), "=r"(r[2]), "=r"(r[3]) : "r"(addr));
}

__device__ __forceinline__ void mma_16816(float* c, const uint32_t* a, uint32_t b0, uint32_t b1) {
    asm volatile(
        "mma.sync.aligned.m16n8k16.row.col.f32.bf16.bf16.f32 "
        "{%0,%1,%2,%3}, {%4,%5,%6,%7}, {%8,%9}, {%0,%1,%2,%3};"
        : "+f"(c[0]), "+f"(c[1]), "+f"(c[2]), "+f"(c[3])
        : "r"(a[0]), "r"(a[1]), "r"(a[2]), "r"(a[3]), "r"(b0), "r"(b1));
}

// ============================================================================
// MX quant-dequant (exact match of the reference semantics)
// ============================================================================
__device__ __forceinline__ float mx_qd(float v, float amax) {
    if (amax == 0.0f) return 0.0f;              // all-zero block
    int e;
    frexpf(amax, &e);                           // amax = m * 2^e, m in [0.5,1)
    int se = (e - 1) - 8;                       // floor(log2(amax)) - 8 (exact)
    se = max(-127, min(127, se));
    float vs = ldexpf(v, -se);                  // v / 2^se, exact
    __nv_fp8_storage_t q = __nv_cvt_float_to_fp8(vs, __NV_SATFINITE, __NV_E4M3);
    __half_raw hr = __nv_cvt_fp8_to_halfraw(q, __NV_E4M3);
    return ldexpf(__half2float(*reinterpret_cast<__half*>(&hr)), se);
}

// ============================================================================
// Vectorized quantize along contiguous dim: 8 lanes x float4 = one 32-block.
// ============================================================================
__global__ void quant_rows_v4(const float4* __restrict__ in, uint2* __restrict__ out) {
    size_t idx = (size_t)blockIdx.x * blockDim.x + threadIdx.x;
    float4 v = in[idx];
    float a = fmaxf(fmaxf(fabsf(v.x), fabsf(v.y)), fmaxf(fabsf(v.z), fabsf(v.w)));
    #pragma unroll
    for (int off = 4; off >= 1; off >>= 1)
        a = fmaxf(a, __shfl_xor_sync(0xFFFFFFFFu, a, off, 8));
    __nv_bfloat16 q0 = __float2bfloat16(mx_qd(v.x, a));
    __nv_bfloat16 q1 = __float2bfloat16(mx_qd(v.y, a));
    __nv_bfloat16 q2 = __float2bfloat16(mx_qd(v.z, a));
    __nv_bfloat16 q3 = __float2bfloat16(mx_qd(v.w, a));
    uint2 o;
    o.x = ((uint32_t)__bfloat16_as_ushort(q1) << 16) | __bfloat16_as_ushort(q0);
    o.y = ((uint32_t)__bfloat16_as_ushort(q3) << 16) | __bfloat16_as_ushort(q2);
    out[idx] = o;
}

// Quantize mat[R, C] along last dim (C, blocks of 32), write transposed [C, R] bf16.
__global__ void quant_transpose_v4(const float* __restrict__ in, __nv_bfloat16* __restrict__ out) {
    __shared__ __nv_bfloat16 tile[32][36];   // [c][r], padded
    const int tid = threadIdx.x;
    const int r0 = blockIdx.y * 32, c0 = blockIdx.x * 32;
    {
        const int r = tid >> 3, cg = tid & 7;
        float4 v = *reinterpret_cast<const float4*>(in + (size_t)(r0 + r) * DIM + c0 + cg * 4);
        float a = fmaxf(fmaxf(fabsf(v.x), fabsf(v.y)), fmaxf(fabsf(v.z), fabsf(v.w)));
        #pragma unroll
        for (int off = 4; off >= 1; off >>= 1)
            a = fmaxf(a, __shfl_xor_sync(0xFFFFFFFFu, a, off, 8));
        tile[cg * 4 + 0][r] = __float2bfloat16(mx_qd(v.x, a));
        tile[cg * 4 + 1][r] = __float2bfloat16(mx_qd(v.y, a));
        tile[cg * 4 + 2][r] = __float2bfloat16(mx_qd(v.z, a));
        tile[cg * 4 + 3][r] = __float2bfloat16(mx_qd(v.w, a));
    }
    __syncthreads();
    {
        const int c = tid >> 3, rg = tid & 7;
        uint2 o = *reinterpret_cast<const uint2*>(&tile[c][rg * 4]);
        *reinterpret_cast<uint2*>(out + (size_t)(c0 + c) * DIM + r0 + rg * 4) = o;
    }
}

// ============================================================================
// bf16 HMMA GEMM: C[m,n] = sum_k A[m,k] * B[n,k]
//   CTA 128x128x64, 256 threads = 8 warps (2m x 4n), warp tile 64x32.
//   3-stage cp.async pipeline; 2 CTAs / SM; precomputed addressing.
// ============================================================================
template <bool REQUANT>
__global__ void __launch_bounds__(256, 2) gemm_bf16_kernel(
    const __nv_bfloat16* __restrict__ A,
    const __nv_bfloat16* __restrict__ B,
    void* __restrict__ Cout)
{
    extern __shared__ char smem[];
    const uint32_t sbase = smem_u32(smem);
    const int tid  = threadIdx.x;
    const int wid  = tid >> 5, lane = tid & 31;
    const int m0   = blockIdx.y * BM, n0 = blockIdx.x * BN;
    const int wm   = (wid >> 2) * 64;   // 0 / 64
    const int wn   = (wid & 3) * 32;    // 0 / 32 / 64 / 96

    const char* Ag = (const char*)(A + (size_t)m0 * DIM);
    const char* Bg = (const char*)(B + (size_t)n0 * DIM);

    // ---- precomputed cp.async addressing: 4 chunks x (row-byte, smem-off) ----
    uint32_t rowbyte[4], soff[4];
    #pragma unroll
    for (int i = 0; i < 4; i++) {
        int lin = tid + i * 256;
        int row = lin >> 3, c = lin & 7;
        rowbyte[i] = (uint32_t)(row * (DIM * 2) + c * 16);
        soff[i]    = (uint32_t)(row * 128 + ((c ^ (row & 7)) << 4));
    }

    auto issue_tile = [&](uint32_t slot, uint32_t k0byte) {
        const uint32_t sA = sbase + slot * STAGE_BYTES;
        const uint32_t sB = sA + TILE_BYTES;
        #pragma unroll
        for (int i = 0; i < 4; i++) {
            const void* gA = Ag + rowbyte[i] + k0byte;
            const void* gB = Bg + rowbyte[i] + k0byte;
            asm volatile("cp.async.cg.shared.global [%0], [%1], 16;" :: "r"(sA + soff[i]), "l"(gA));
            asm volatile("cp.async.cg.shared.global [%0], [%1], 16;" :: "r"(sB + soff[i]), "l"(gB));
        }
        asm volatile("cp.async.commit_group;" ::: "memory");
    };

    // ---- per-lane ldmatrix addressing: precomputed rows + swizzled columns ----
    const int sw  = lane & 7;
    const int ahi = lane >> 4;
    const int bhi = (lane >> 3) & 1;
    uint32_t aRowOff[4], bRowOff[2], acol[4], bcol[4];
    #pragma unroll
    for (int mi = 0; mi < 4; mi++)
        aRowOff[mi] = (wm + mi * 16 + (lane & 7) + ((lane >> 3) & 1) * 8) * 128;
    #pragma unroll
    for (int nj = 0; nj < 2; nj++)
        bRowOff[nj] = (wn + nj * 16 + (lane & 7) + (lane >> 4) * 8) * 128;
    #pragma unroll
    for (int ks = 0; ks < 4; ks++) {
        acol[ks] = (uint32_t)(((ks * 2 + ahi) ^ sw) << 4);
        bcol[ks] = (uint32_t)(((ks * 2 + bhi) ^ sw) << 4);
    }

    float acc[4][4][4];
    #pragma unroll
    for (int mi = 0; mi < 4; mi++)
        #pragma unroll
        for (int ni = 0; ni < 4; ni++)
            #pragma unroll
            for (int j = 0; j < 4; j++) acc[mi][ni][j] = 0.0f;

    // ---- pipeline prologue: fill 2 of 3 stages ----
    issue_tile(0, 0);
    issue_tile(1, BK_BYTES);

    int slotC = 0, slotP = 2;
    uint32_t kbyte_next = 2 * BK_BYTES;

    for (int kt = 0; kt < NKITER; kt++) {
        asm volatile("cp.async.wait_group 1;" ::: "memory");  // tile kt resident
        __syncthreads();

        if (kt + 2 < NKITER) {
            issue_tile((uint32_t)slotP, kbyte_next);
            kbyte_next += BK_BYTES;
        } else {
            asm volatile("cp.async.commit_group;" ::: "memory");  // keep group count
        }

        const uint32_t sA = sbase + (uint32_t)slotC * STAGE_BYTES;
        const uint32_t sB = sA + TILE_BYTES;

        #pragma unroll
        for (int ks = 0; ks < BK / 16; ks++) {
            uint32_t afr[4][4], bfr[2][4];
            #pragma unroll
            for (int mi = 0; mi < 4; mi++) ldmatrix_x4(afr[mi], sA + aRowOff[mi] + acol[ks]);
            #pragma unroll
            for (int nj = 0; nj < 2; nj++) ldmatrix_x4(bfr[nj], sB + bRowOff[nj] + bcol[ks]);
            #pragma unroll
            for (int mi = 0; mi < 4; mi++)
                #pragma unroll
                for (int ni = 0; ni < 4; ni++)
                    mma_16816(acc[mi][ni], afr[mi],
                              bfr[ni >> 1][(ni & 1) * 2], bfr[ni >> 1][(ni & 1) * 2 + 1]);
        }

        slotC = (slotC == STAGES - 1) ? 0 : slotC + 1;
        slotP = (slotP == STAGES - 1) ? 0 : slotP + 1;
    }

    // ---- epilogue ----
    const int tr = lane >> 2, tc = (lane & 3) * 2;
    if (!REQUANT) {
        float* C = (float*)Cout;
        #pragma unroll
        for (int mi = 0; mi < 4; mi++) {
            const int m = m0 + wm + mi * 16 + tr;
            #pragma unroll
            for (int ni = 0; ni < 4; ni++) {
                const int n = n0 + wn + ni * 8 + tc;
                *reinterpret_cast<float2*>(C + (size_t)m * DIM + n) =
                    make_float2(acc[mi][ni][0], acc[mi][ni][1]);
                *reinterpret_cast<float2*>(C + (size_t)(m + 8) * DIM + n) =
                    make_float2(acc[mi][ni][2], acc[mi][ni][3]);
            }
        }
    } else {
        // Warp's N-range [n0+wn, n0+wn+32) is exactly one MX block per row.
        __nv_bfloat16* C = (__nv_bfloat16*)Cout;
        #pragma unroll
        for (int mi = 0; mi < 4; mi++) {
            #pragma unroll
            for (int h = 0; h < 2; h++) {          // row tr  /  row tr+8
                float a = 0.0f;
                #pragma unroll
                for (int ni = 0; ni < 4; ni++)
                    a = fmaxf(a, fmaxf(fabsf(acc[mi][ni][2 * h]), fabsf(acc[mi][ni][2 * h + 1])));
                a = fmaxf(a, __shfl_xor_sync(0xFFFFFFFFu, a, 1, 4));
                a = fmaxf(a, __shfl_xor_sync(0xFFFFFFFFu, a, 2, 4));
                const int m = m0 + wm + mi * 16 + h * 8 + tr;
                #pragma unroll
                for (int ni = 0; ni < 4; ni++) {
                    const int n = n0 + wn + ni * 8 + tc;
                    __nv_bfloat16 q0 = __float2bfloat16(mx_qd(acc[mi][ni][2 * h], a));
                    __nv_bfloat16 q1 = __float2bfloat16(mx_qd(acc[mi][ni][2 * h + 1], a));
                    uint32_t pk = ((uint32_t)__bfloat16_as_ushort(q1) << 16) |
                                  __bfloat16_as_ushort(q0);
                    *reinterpret_cast<uint32_t*>(C + (size_t)m * DIM + n) = pk;
                }
            }
        }
    }
}

// ============================================================================
// Host side
// ============================================================================
extern "C" void kernel_launch(void* const* d_in, const int* in_sizes, int n_in,
                              void* d_out, int out_size) {
    const float* x_mx = (const float*)d_in[0];
    const float* mat1 = (const float*)d_in[1];
    const float* mat2 = (const float*)d_in[2];
    float* out = (float*)d_out;

    void *pX, *pW1T, *pW2T, *pH2;
    cudaGetSymbolAddress(&pX,   g_X);
    cudaGetSymbolAddress(&pW1T, g_W1T);
    cudaGetSymbolAddress(&pW2T, g_W2T);
    cudaGetSymbolAddress(&pH2,  g_H2);

    // One-time side-stream / event setup (runs on the first, non-captured
    // correctness call; reused identically on every later call so the
    // captured graph is deterministic).
    static cudaStream_t s1 = nullptr, s2 = nullptr, s3 = nullptr;
    static cudaEvent_t eFork = nullptr, eX = nullptr, eW1 = nullptr, eW2 = nullptr;
    if (s1 == nullptr) {
        cudaStreamCreateWithFlags(&s1, cudaStreamNonBlocking);
        cudaStreamCreateWithFlags(&s2, cudaStreamNonBlocking);
        cudaStreamCreateWithFlags(&s3, cudaStreamNonBlocking);
        cudaEventCreateWithFlags(&eFork, cudaEventDisableTiming);
        cudaEventCreateWithFlags(&eX,    cudaEventDisableTiming);
        cudaEventCreateWithFlags(&eW1,   cudaEventDisableTiming);
        cudaEventCreateWithFlags(&eW2,   cudaEventDisableTiming);
        cudaFuncSetAttribute(gemm_bf16_kernel<false>,
                             cudaFuncAttributeMaxDynamicSharedMemorySize, SMEM_TOTAL);
        cudaFuncSetAttribute(gemm_bf16_kernel<true>,
                             cudaFuncAttributeMaxDynamicSharedMemorySize, SMEM_TOTAL);
    }

    dim3 tgrid(DIM / 32, DIM / 32);
    dim3 ggrid(DIM / BN, DIM / BM);

    // ---- fork: three quant kernels run concurrently on side streams ----
    cudaEventRecord(eFork, 0);
    cudaStreamWaitEvent(s1, eFork, 0);
    cudaStreamWaitEvent(s2, eFork, 0);
    cudaStreamWaitEvent(s3, eFork, 0);

    quant_rows_v4<<<(unsigned)(NELEM / 1024), 256, 0, s1>>>((const float4*)x_mx, (uint2*)pX);
    cudaEventRecord(eX, s1);
    quant_transpose_v4<<<tgrid, 256, 0, s2>>>(mat1, (__nv_bfloat16*)pW1T);
    cudaEventRecord(eW1, s2);
    quant_transpose_v4<<<tgrid, 256, 0, s3>>>(mat2, (__nv_bfloat16*)pW2T);
    cudaEventRecord(eW2, s3);

    // ---- GEMM1 needs X + W1T; W2T quant overlaps it on s3 ----
    cudaStreamWaitEvent(0, eX, 0);
    cudaStreamWaitEvent(0, eW1, 0);
    gemm_bf16_kernel<true><<<ggrid, 256, SMEM_TOTAL>>>(
        (const __nv_bfloat16*)pX, (const __nv_bfloat16*)pW1T, pH2);

    // ---- GEMM2 additionally needs W2T ----
    cudaStreamWaitEvent(0, eW2, 0);
    gemm_bf16_kernel<false><<<ggrid, 256, SMEM_TOTAL>>>(
        (const __nv_bfloat16*)pH2, (const __nv_bfloat16*)pW2T, out);
}